// round 2
// baseline (speedup 1.0000x reference)
#include <cuda_runtime.h>
#include <math_constants.h>

#define WML    64
#define BATCH  64
#define SENTS  40
#define DIM    512
#define NWORDS (SENTS * WML)   /* 2560 */
#define WSPLIT 16
#define WPC    (WML / WSPLIT)  /* 4 w-values per CTA, one per warp */
#define BS     8               /* sentences per softmax block */

/* ------------------- scratch (static device memory; no allocs) -------- */
__device__ float g_qword[BATCH * DIM];
__device__ float g_qsent[BATCH * DIM];
__device__ float g_ssa[BATCH * SENTS];
__device__ float g_scores[BATCH * NWORDS];
__device__ float g_partM[BATCH * WSPLIT];
__device__ float g_partL[BATCH * WSPLIT];
__device__ float g_partAcc[BATCH * WSPLIT * DIM];
__device__ float g_c[BATCH * DIM];

/* ------------------- K0: q_word / q_sent projections ------------------ */
__global__ void qproj_kernel(const float* __restrict__ src,
                             const float* __restrict__ Wword,
                             const float* __restrict__ Wsent) {
    const float* W   = blockIdx.y ? Wsent : Wword;
    float*       out = blockIdx.y ? g_qsent : g_qword;
    const int dt = blockIdx.x * 64;

    __shared__ float As[64][65];
    __shared__ float Bs[64][65];
    const int tid = threadIdx.x;
    const int tx = tid & 15, ty = tid >> 4;
    float acc[4][4] = {};

    for (int k0 = 0; k0 < DIM; k0 += 64) {
        for (int i = tid; i < 4096; i += 256) {
            int r = i >> 6, c = i & 63;
            As[r][c] = src[r * DIM + k0 + c];
            Bs[r][c] = W[(dt + r) * DIM + k0 + c];
        }
        __syncthreads();
        #pragma unroll 8
        for (int kk = 0; kk < 64; kk++) {
            float a[4], w[4];
            #pragma unroll
            for (int i = 0; i < 4; i++) a[i] = As[ty * 4 + i][kk];
            #pragma unroll
            for (int j = 0; j < 4; j++) w[j] = Bs[tx * 4 + j][kk];
            #pragma unroll
            for (int i = 0; i < 4; i++)
                #pragma unroll
                for (int j = 0; j < 4; j++) acc[i][j] += a[i] * w[j];
        }
        __syncthreads();
    }
    #pragma unroll
    for (int i = 0; i < 4; i++)
        #pragma unroll
        for (int j = 0; j < 4; j++)
            out[(ty * 4 + i) * DIM + dt + tx * 4 + j] = acc[i][j];
}

/* ------------------- K1: ssa[b][s] = (q_sent . sent_v) * static ------- */
__global__ void sentscore_kernel(const float* __restrict__ sent_bank,
                                 const float* __restrict__ static_attn) {
    const int b = blockIdx.x;
    const int tid = threadIdx.x;
    __shared__ float sq[DIM];
    for (int i = tid; i < DIM; i += 256) sq[i] = g_qsent[b * DIM + i];
    __syncthreads();

    const int wp = tid >> 5, ln = tid & 31;
    const float4* q4 = (const float4*)sq;
    for (int s = wp; s < SENTS; s += 8) {
        const float4* v4 = (const float4*)(sent_bank + ((size_t)s * BATCH + b) * DIM);
        float dot = 0.f;
        #pragma unroll
        for (int k = 0; k < 4; k++) {
            float4 q = q4[ln + 32 * k];
            float4 v = v4[ln + 32 * k];
            dot += q.x * v.x + q.y * v.y + q.z * v.z + q.w * v.w;
        }
        #pragma unroll
        for (int off = 16; off > 0; off >>= 1)
            dot += __shfl_xor_sync(0xffffffffu, dot, off);
        if (ln == 0) g_ssa[b * SENTS + s] = dot * static_attn[b * SENTS + s];
    }
}

/* ------------------- K2: fused score + block softmax + weighted sum --- */
/* grid (WSPLIT, BATCH) = 1024 CTAs, 128 thr (4 warps). Warp wp owns     */
/* w = sp*WPC+wp, streams its contiguous (w,b) chunk of 80KB.            */
/* Per block of BS sentences: compute all dots (pipelined shfl chains),  */
/* block max, ONE accumulator rescale, then reload v from L1 for p*v.    */
__global__ void __launch_bounds__(128, 6)
main_kernel(const float* __restrict__ word_bank,
            const int*   __restrict__ word_lengths) {
    const int b = blockIdx.y, sp = blockIdx.x;
    const int tid = threadIdx.x, wp = tid >> 5, ln = tid & 31;

    __shared__ float sq[DIM];
    __shared__ float sssa[SENTS];
    __shared__ int   swl[SENTS];
    __shared__ float racc[WPC][DIM];
    __shared__ float rm[WPC], rl[WPC];

    for (int i = tid; i < DIM; i += 128) sq[i] = g_qword[b * DIM + i];
    if (tid < SENTS) {
        sssa[tid] = g_ssa[b * SENTS + tid];
        swl[tid]  = word_lengths[b * SENTS + tid];
    }
    __syncthreads();

    const int w = sp * WPC + wp;
    const float4* q4 = (const float4*)sq;
    const float4 q0 = q4[ln], q1 = q4[ln + 32], q2 = q4[ln + 64], q3 = q4[ln + 96];
    const float* base = word_bank + ((size_t)w * BATCH + b) * (size_t)(SENTS * DIM);

    float m = -CUDART_INF_F, l = 0.f;
    float4 a0 = {0,0,0,0}, a1 = {0,0,0,0}, a2 = {0,0,0,0}, a3 = {0,0,0,0};

    for (int s0 = 0; s0 < SENTS; s0 += BS) {
        /* phase 1: BS independent partial dots (high MLP) */
        float pd[BS];
        #pragma unroll
        for (int i = 0; i < BS; i++) {
            const float4* v4 = (const float4*)(base + (size_t)(s0 + i) * DIM);
            float4 v0 = v4[ln], v1 = v4[ln + 32], v2 = v4[ln + 64], v3 = v4[ln + 96];
            pd[i] = v0.x*q0.x + v0.y*q0.y + v0.z*q0.z + v0.w*q0.w
                  + v1.x*q1.x + v1.y*q1.y + v1.z*q1.z + v1.w*q1.w
                  + v2.x*q2.x + v2.y*q2.y + v2.z*q2.z + v2.w*q2.w
                  + v3.x*q3.x + v3.y*q3.y + v3.z*q3.z + v3.w*q3.w;
        }
        /* phase 2: BS shuffle-reduce chains, latency-pipelined */
        #pragma unroll
        for (int i = 0; i < BS; i++) {
            #pragma unroll
            for (int off = 16; off > 0; off >>= 1)
                pd[i] += __shfl_xor_sync(0xffffffffu, pd[i], off);
        }
        /* phase 3: scores + block max */
        float bmax = -CUDART_INF_F;
        #pragma unroll
        for (int i = 0; i < BS; i++) {
            const bool valid = (w < swl[s0 + i]);
            const float scv = valid ? pd[i] * sssa[s0 + i] : -CUDART_INF_F;
            pd[i] = scv;
            bmax = fmaxf(bmax, scv);
            if (ln == 0) g_scores[(size_t)b * NWORDS + (s0 + i) * WML + w] = scv;
        }
        /* phase 4: one rescale, then reload (L1 hit) + accumulate */
        const float mn = fmaxf(m, bmax);
        if (mn != -CUDART_INF_F) {
            const float scale = __expf(m - mn);   /* m=-inf -> 0 */
            l *= scale;
            a0.x *= scale; a0.y *= scale; a0.z *= scale; a0.w *= scale;
            a1.x *= scale; a1.y *= scale; a1.z *= scale; a1.w *= scale;
            a2.x *= scale; a2.y *= scale; a2.z *= scale; a2.w *= scale;
            a3.x *= scale; a3.y *= scale; a3.z *= scale; a3.w *= scale;
            #pragma unroll
            for (int i = 0; i < BS; i++) {
                const float p = __expf(pd[i] - mn);   /* -inf -> 0 */
                if (p > 0.f) {
                    l += p;
                    const float4* v4 = (const float4*)(base + (size_t)(s0 + i) * DIM);
                    float4 v0 = v4[ln], v1 = v4[ln + 32], v2 = v4[ln + 64], v3 = v4[ln + 96];
                    a0.x += p * v0.x; a0.y += p * v0.y; a0.z += p * v0.z; a0.w += p * v0.w;
                    a1.x += p * v1.x; a1.y += p * v1.y; a1.z += p * v1.z; a1.w += p * v1.w;
                    a2.x += p * v2.x; a2.y += p * v2.y; a2.z += p * v2.z; a2.w += p * v2.w;
                    a3.x += p * v3.x; a3.y += p * v3.y; a3.z += p * v3.z; a3.w += p * v3.w;
                }
            }
            m = mn;
        }
    }

    /* CTA combine of 4 warp partials -> per-split partial */
    float4* r4 = (float4*)racc[wp];
    r4[ln] = a0; r4[ln + 32] = a1; r4[ln + 64] = a2; r4[ln + 96] = a3;
    if (ln == 0) { rm[wp] = m; rl[wp] = l; }
    __syncthreads();

    float mC = -CUDART_INF_F;
    #pragma unroll
    for (int i = 0; i < WPC; i++) mC = fmaxf(mC, rm[i]);

    #pragma unroll
    for (int rr = 0; rr < 4; rr++) {
        const int d = tid + rr * 128;
        float sacc = 0.f;
        #pragma unroll
        for (int i = 0; i < WPC; i++) {
            float sc = (rm[i] == -CUDART_INF_F) ? 0.f : __expf(rm[i] - mC);
            sacc += racc[i][d] * sc;
        }
        g_partAcc[((size_t)b * WSPLIT + sp) * DIM + d] = sacc;
    }
    if (tid == 0) {
        float L = 0.f;
        #pragma unroll
        for (int i = 0; i < WPC; i++) {
            float sc = (rm[i] == -CUDART_INF_F) ? 0.f : __expf(rm[i] - mC);
            L += rl[i] * sc;
        }
        g_partM[b * WSPLIT + sp] = mC;
        g_partL[b * WSPLIT + sp] = L;
    }
}

/* ------------------- K3a: merge splits -> c and align_vectors --------- */
/* grid (BATCH, 5), 512 thr. y==0: c vector; y=1..4: align quarter.      */
__global__ void combine_kernel(float* __restrict__ align_out, int has_align) {
    const int b = blockIdx.x, part = blockIdx.y, tid = threadIdx.x;
    __shared__ float sScale[WSPLIT];
    __shared__ float sM, sL;

    if (tid == 0) {
        float M = -CUDART_INF_F;
        #pragma unroll
        for (int i = 0; i < WSPLIT; i++) M = fmaxf(M, g_partM[b * WSPLIT + i]);
        float L = 0.f;
        #pragma unroll
        for (int i = 0; i < WSPLIT; i++) {
            float mi = g_partM[b * WSPLIT + i];
            float sc = (mi == -CUDART_INF_F) ? 0.f : __expf(mi - M);
            sScale[i] = sc;
            L += g_partL[b * WSPLIT + i] * sc;
        }
        sM = M; sL = L;
    }
    __syncthreads();
    const float M = sM;
    const float invL = 1.f / sL;

    if (part == 0) {
        float c = 0.f;
        #pragma unroll
        for (int i = 0; i < WSPLIT; i++)
            c += g_partAcc[((size_t)b * WSPLIT + i) * DIM + tid] * sScale[i];
        g_c[b * DIM + tid] = c * invL;
    } else if (has_align) {
        const int n0 = (part - 1) * (NWORDS / 4);
        for (int n = tid; n < NWORDS / 4; n += 512) {
            float s = g_scores[(size_t)b * NWORDS + n0 + n];
            align_out[(size_t)b * NWORDS + n0 + n] = __expf(s - M) * invL + 1e-20f;
        }
    }
}

/* ------------------- K3b: attn_h = tanh([c, source] @ W_out^T) -------- */
__global__ void outproj_kernel(const float* __restrict__ src,
                               const float* __restrict__ Wout,
                               float* __restrict__ attn_out) {
    const int dt = blockIdx.x * 64;
    __shared__ float As[64][65];
    __shared__ float Bs[64][65];
    const int tid = threadIdx.x;
    const int tx = tid & 15, ty = tid >> 4;
    float acc[4][4] = {};

    for (int k0 = 0; k0 < 2 * DIM; k0 += 64) {
        for (int i = tid; i < 4096; i += 256) {
            int r = i >> 6, c = i & 63;
            int k = k0 + c;
            As[r][c] = (k < DIM) ? g_c[r * DIM + k] : src[r * DIM + (k - DIM)];
            Bs[r][c] = Wout[(dt + r) * (2 * DIM) + k];
        }
        __syncthreads();
        #pragma unroll 8
        for (int kk = 0; kk < 64; kk++) {
            float a[4], w[4];
            #pragma unroll
            for (int i = 0; i < 4; i++) a[i] = As[ty * 4 + i][kk];
            #pragma unroll
            for (int j = 0; j < 4; j++) w[j] = Bs[tx * 4 + j][kk];
            #pragma unroll
            for (int i = 0; i < 4; i++)
                #pragma unroll
                for (int j = 0; j < 4; j++) acc[i][j] += a[i] * w[j];
        }
        __syncthreads();
    }
    #pragma unroll
    for (int i = 0; i < 4; i++)
        #pragma unroll
        for (int j = 0; j < 4; j++)
            attn_out[(ty * 4 + i) * DIM + dt + tx * 4 + j] = tanhf(acc[i][j]);
}

/* ------------------- launch ------------------------------------------- */
extern "C" void kernel_launch(void* const* d_in, const int* in_sizes, int n_in,
                              void* d_out, int out_size) {
    const float* source       = (const float*)d_in[0];
    const float* word_bank    = (const float*)d_in[1];
    const int*   word_lengths = (const int*)  d_in[2];
    const float* sent_bank    = (const float*)d_in[3];
    /* d_in[4] = sent_lengths: unused by the forward math */
    const float* static_attn  = (const float*)d_in[5];
    const float* W_word       = (const float*)d_in[6];
    const float* W_sent       = (const float*)d_in[7];
    const float* W_out        = (const float*)d_in[8];

    float* attn_out  = (float*)d_out;
    const int need   = BATCH * DIM + BATCH * NWORDS;
    const int has_align = (out_size >= need) ? 1 : 0;
    float* align_out = attn_out + BATCH * DIM;

    qproj_kernel<<<dim3(DIM / 64, 2), 256>>>(source, W_word, W_sent);
    sentscore_kernel<<<BATCH, 256>>>(sent_bank, static_attn);
    main_kernel<<<dim3(WSPLIT, BATCH), 128>>>(word_bank, word_lengths);
    combine_kernel<<<dim3(BATCH, 5), 512>>>(align_out, has_align);
    outproj_kernel<<<DIM / 64, 256>>>(source, W_out, attn_out);
}

// round 3
// speedup vs baseline: 1.4100x; 1.4100x over previous
#include <cuda_runtime.h>
#include <math_constants.h>

#define WML    64
#define BATCH  64
#define SENTS  40
#define DIM    512
#define NWORDS (SENTS * WML)   /* 2560 */

#define TILE_FLOATS (SENTS * DIM)          /* 20480 floats = 80 KB */
#define TILE_F4     (TILE_FLOATS / 4)      /* 5120 float4 */
#define NGROUPS     5                      /* 8 sentences per cp.async group */
#define DYN_SMEM    (TILE_FLOATS * 4)      /* 81920 bytes */

/* ------------------- scratch (static device memory; no allocs) -------- */
__device__ float g_qword[BATCH * DIM];
__device__ float g_qsent[BATCH * DIM];
__device__ float g_ssa[BATCH * SENTS];
__device__ float g_scores[BATCH * NWORDS];
__device__ float g_partM[BATCH * WML];
__device__ float g_partL[BATCH * WML];
__device__ float g_partAcc[(size_t)BATCH * WML * DIM];   /* 8 MB */
__device__ float g_c[BATCH * DIM];

/* ------------------- K0: q_word / q_sent projections ------------------ */
__global__ void qproj_kernel(const float* __restrict__ src,
                             const float* __restrict__ Wword,
                             const float* __restrict__ Wsent) {
    const float* W   = blockIdx.y ? Wsent : Wword;
    float*       out = blockIdx.y ? g_qsent : g_qword;
    const int dt = blockIdx.x * 64;

    __shared__ float As[64][65];
    __shared__ float Bs[64][65];
    const int tid = threadIdx.x;
    const int tx = tid & 15, ty = tid >> 4;
    float acc[4][4] = {};

    for (int k0 = 0; k0 < DIM; k0 += 64) {
        for (int i = tid; i < 4096; i += 256) {
            int r = i >> 6, c = i & 63;
            As[r][c] = src[r * DIM + k0 + c];
            Bs[r][c] = W[(dt + r) * DIM + k0 + c];
        }
        __syncthreads();
        #pragma unroll 8
        for (int kk = 0; kk < 64; kk++) {
            float a[4], w[4];
            #pragma unroll
            for (int i = 0; i < 4; i++) a[i] = As[ty * 4 + i][kk];
            #pragma unroll
            for (int j = 0; j < 4; j++) w[j] = Bs[tx * 4 + j][kk];
            #pragma unroll
            for (int i = 0; i < 4; i++)
                #pragma unroll
                for (int j = 0; j < 4; j++) acc[i][j] += a[i] * w[j];
        }
        __syncthreads();
    }
    #pragma unroll
    for (int i = 0; i < 4; i++)
        #pragma unroll
        for (int j = 0; j < 4; j++)
            out[(ty * 4 + i) * DIM + dt + tx * 4 + j] = acc[i][j];
}

/* ------------------- K1: ssa[b][s] = (q_sent . sent_v) * static ------- */
__global__ void sentscore_kernel(const float* __restrict__ sent_bank,
                                 const float* __restrict__ static_attn) {
    const int b = blockIdx.x;
    const int tid = threadIdx.x;
    __shared__ float sq[DIM];
    for (int i = tid; i < DIM; i += 256) sq[i] = g_qsent[b * DIM + i];
    __syncthreads();

    const int wp = tid >> 5, ln = tid & 31;
    const float4* q4 = (const float4*)sq;
    for (int s = wp; s < SENTS; s += 8) {
        const float4* v4 = (const float4*)(sent_bank + ((size_t)s * BATCH + b) * DIM);
        float dot = 0.f;
        #pragma unroll
        for (int k = 0; k < 4; k++) {
            float4 q = q4[ln + 32 * k];
            float4 v = v4[ln + 32 * k];
            dot += q.x * v.x + q.y * v.y + q.z * v.z + q.w * v.w;
        }
        #pragma unroll
        for (int off = 16; off > 0; off >>= 1)
            dot += __shfl_xor_sync(0xffffffffu, dot, off);
        if (ln == 0) g_ssa[b * SENTS + s] = dot * static_attn[b * SENTS + s];
    }
}

/* ------------------- K2: per-(w,b) CTA, smem-resident tile ------------ */
/* grid (WML, BATCH) = 4096 CTAs, 256 thr. cp.async streams the 80KB     */
/* chunk into smem in 5 groups; dots chase the groups; softmax + weighted */
/* sum are served entirely from smem. One DRAM pass, no serial chains.   */
__global__ void __launch_bounds__(256, 2)
main_kernel(const float* __restrict__ word_bank,
            const int*   __restrict__ word_lengths) {
    extern __shared__ float s_tile[];          /* [SENTS][DIM] */
    __shared__ float s_q[DIM];
    __shared__ float s_p[SENTS];               /* scores, then p values */
    __shared__ float s_ssa[SENTS];
    __shared__ int   s_wl[SENTS];

    const int b = blockIdx.y, w = blockIdx.x;
    const int tid = threadIdx.x, wp = tid >> 5, ln = tid & 31;
    const float* base = word_bank + ((size_t)w * BATCH + b) * (size_t)TILE_FLOATS;

    /* ---- issue all cp.async groups (8 sentences / group) ---- */
    {
        const float4* src = (const float4*)base;
        unsigned dst_base = (unsigned)__cvta_generic_to_shared(s_tile);
        #pragma unroll
        for (int g = 0; g < NGROUPS; g++) {
            #pragma unroll
            for (int j = 0; j < 4; j++) {
                int idx = g * 1024 + j * 256 + tid;   /* float4 index */
                asm volatile("cp.async.cg.shared.global [%0], [%1], 16;\n"
                             :: "r"(dst_base + idx * 16), "l"(src + idx));
            }
            asm volatile("cp.async.commit_group;\n");
        }
    }

    /* ---- small loads while copies fly ---- */
    for (int i = tid; i < DIM; i += 256) s_q[i] = g_qword[b * DIM + i];
    if (tid < SENTS) {
        s_ssa[tid] = g_ssa[b * SENTS + tid];
        s_wl[tid]  = word_lengths[b * SENTS + tid];
    }
    __syncthreads();

    const float4* q4 = (const float4*)s_q;
    const float4 q0 = q4[ln], q1 = q4[ln + 32], q2 = q4[ln + 64], q3 = q4[ln + 96];

    /* ---- dots: warp wp handles sentence 8c + wp of each chunk ---- */
    #pragma unroll
    for (int c = 0; c < NGROUPS; c++) {
        switch (c) {   /* wait until groups 0..c complete */
            case 0: asm volatile("cp.async.wait_group 4;\n"); break;
            case 1: asm volatile("cp.async.wait_group 3;\n"); break;
            case 2: asm volatile("cp.async.wait_group 2;\n"); break;
            case 3: asm volatile("cp.async.wait_group 1;\n"); break;
            default: asm volatile("cp.async.wait_group 0;\n"); break;
        }
        __syncthreads();
        const int s = c * 8 + wp;
        const float4* v4 = (const float4*)(s_tile + s * DIM);
        float4 v0 = v4[ln], v1 = v4[ln + 32], v2 = v4[ln + 64], v3 = v4[ln + 96];
        float dot = v0.x*q0.x + v0.y*q0.y + v0.z*q0.z + v0.w*q0.w
                  + v1.x*q1.x + v1.y*q1.y + v1.z*q1.z + v1.w*q1.w
                  + v2.x*q2.x + v2.y*q2.y + v2.z*q2.z + v2.w*q2.w
                  + v3.x*q3.x + v3.y*q3.y + v3.z*q3.z + v3.w*q3.w;
        #pragma unroll
        for (int off = 16; off > 0; off >>= 1)
            dot += __shfl_xor_sync(0xffffffffu, dot, off);
        if (ln == 0) {
            const bool valid = (w < s_wl[s]);
            const float scv = valid ? dot * s_ssa[s] : -CUDART_INF_F;
            s_p[s] = scv;
            g_scores[(size_t)b * NWORDS + s * WML + w] = scv;
        }
    }
    __syncthreads();

    /* ---- softmax over the 40 scores (warp 0) ---- */
    if (wp == 0) {
        float v1 = s_p[ln];
        float v2 = (ln < 8) ? s_p[32 + ln] : -CUDART_INF_F;
        float mx = fmaxf(v1, v2);
        #pragma unroll
        for (int off = 16; off > 0; off >>= 1)
            mx = fmaxf(mx, __shfl_xor_sync(0xffffffffu, mx, off));
        float p1 = (mx == -CUDART_INF_F) ? 0.f : __expf(v1 - mx);
        float p2 = (mx == -CUDART_INF_F || ln >= 8) ? 0.f : __expf(v2 - mx);
        float l = p1 + p2;
        #pragma unroll
        for (int off = 16; off > 0; off >>= 1)
            l += __shfl_xor_sync(0xffffffffu, l, off);
        s_p[ln] = p1;
        if (ln < 8) s_p[32 + ln] = p2;
        if (ln == 0) {
            g_partM[b * WML + w] = mx;
            g_partL[b * WML + w] = l;
        }
    }
    __syncthreads();

    /* ---- weighted sum from smem: thread t owns dims t, t+256 ---- */
    #pragma unroll
    for (int r = 0; r < 2; r++) {
        const int d = tid + r * 256;
        float acc = 0.f;
        #pragma unroll 8
        for (int s = 0; s < SENTS; s++)
            acc += s_p[s] * s_tile[s * DIM + d];
        g_partAcc[((size_t)b * WML + w) * DIM + d] = acc;
    }
}

/* ------------------- K3a: merge 64 splits -> c and align -------------- */
/* grid (BATCH, 5), 512 thr. y==0: c vector; y=1..4: align quarter.      */
__global__ void combine_kernel(float* __restrict__ align_out, int has_align) {
    const int b = blockIdx.x, part = blockIdx.y, tid = threadIdx.x;
    __shared__ float sScale[WML];
    __shared__ float sM, sL;

    if (tid < 32) {
        /* warp 0 computes M, L over 64 splits */
        float m1 = g_partM[b * WML + tid];
        float m2 = g_partM[b * WML + 32 + tid];
        float mx = fmaxf(m1, m2);
        #pragma unroll
        for (int off = 16; off > 0; off >>= 1)
            mx = fmaxf(mx, __shfl_xor_sync(0xffffffffu, mx, off));
        float sc1 = (m1 == -CUDART_INF_F) ? 0.f : __expf(m1 - mx);
        float sc2 = (m2 == -CUDART_INF_F) ? 0.f : __expf(m2 - mx);
        float l = g_partL[b * WML + tid] * sc1 + g_partL[b * WML + 32 + tid] * sc2;
        #pragma unroll
        for (int off = 16; off > 0; off >>= 1)
            l += __shfl_xor_sync(0xffffffffu, l, off);
        sScale[tid] = sc1;
        sScale[32 + tid] = sc2;
        if (tid == 0) { sM = mx; sL = l; }
    }
    __syncthreads();
    const float M = sM;
    const float invL = 1.f / sL;

    if (part == 0) {
        float c = 0.f;
        #pragma unroll 8
        for (int i = 0; i < WML; i++)
            c += g_partAcc[((size_t)b * WML + i) * DIM + tid] * sScale[i];
        g_c[b * DIM + tid] = c * invL;
    } else if (has_align) {
        const int n0 = (part - 1) * (NWORDS / 4);
        for (int n = tid; n < NWORDS / 4; n += 512) {
            float s = g_scores[(size_t)b * NWORDS + n0 + n];
            align_out[(size_t)b * NWORDS + n0 + n] = __expf(s - M) * invL + 1e-20f;
        }
    }
}

/* ------------------- K3b: attn_h = tanh([c, source] @ W_out^T) -------- */
__global__ void outproj_kernel(const float* __restrict__ src,
                               const float* __restrict__ Wout,
                               float* __restrict__ attn_out) {
    const int dt = blockIdx.x * 64;
    __shared__ float As[64][65];
    __shared__ float Bs[64][65];
    const int tid = threadIdx.x;
    const int tx = tid & 15, ty = tid >> 4;
    float acc[4][4] = {};

    for (int k0 = 0; k0 < 2 * DIM; k0 += 64) {
        for (int i = tid; i < 4096; i += 256) {
            int r = i >> 6, c = i & 63;
            int k = k0 + c;
            As[r][c] = (k < DIM) ? g_c[r * DIM + k] : src[r * DIM + (k - DIM)];
            Bs[r][c] = Wout[(dt + r) * (2 * DIM) + k];
        }
        __syncthreads();
        #pragma unroll 8
        for (int kk = 0; kk < 64; kk++) {
            float a[4], w[4];
            #pragma unroll
            for (int i = 0; i < 4; i++) a[i] = As[ty * 4 + i][kk];
            #pragma unroll
            for (int j = 0; j < 4; j++) w[j] = Bs[tx * 4 + j][kk];
            #pragma unroll
            for (int i = 0; i < 4; i++)
                #pragma unroll
                for (int j = 0; j < 4; j++) acc[i][j] += a[i] * w[j];
        }
        __syncthreads();
    }
    #pragma unroll
    for (int i = 0; i < 4; i++)
        #pragma unroll
        for (int j = 0; j < 4; j++)
            attn_out[(ty * 4 + i) * DIM + dt + tx * 4 + j] = tanhf(acc[i][j]);
}

/* ------------------- launch ------------------------------------------- */
extern "C" void kernel_launch(void* const* d_in, const int* in_sizes, int n_in,
                              void* d_out, int out_size) {
    const float* source       = (const float*)d_in[0];
    const float* word_bank    = (const float*)d_in[1];
    const int*   word_lengths = (const int*)  d_in[2];
    const float* sent_bank    = (const float*)d_in[3];
    /* d_in[4] = sent_lengths: unused by forward math */
    const float* static_attn  = (const float*)d_in[5];
    const float* W_word       = (const float*)d_in[6];
    const float* W_sent       = (const float*)d_in[7];
    const float* W_out        = (const float*)d_in[8];

    float* attn_out  = (float*)d_out;
    const int need   = BATCH * DIM + BATCH * NWORDS;
    const int has_align = (out_size >= need) ? 1 : 0;
    float* align_out = attn_out + BATCH * DIM;

    cudaFuncSetAttribute(main_kernel,
                         cudaFuncAttributeMaxDynamicSharedMemorySize, DYN_SMEM);

    qproj_kernel<<<dim3(DIM / 64, 2), 256>>>(source, W_word, W_sent);
    sentscore_kernel<<<BATCH, 256>>>(sent_bank, static_attn);
    main_kernel<<<dim3(WML, BATCH), 256, DYN_SMEM>>>(word_bank, word_lengths);
    combine_kernel<<<dim3(BATCH, 5), 512>>>(align_out, has_align);
    outproj_kernel<<<DIM / 64, 256>>>(source, W_out, attn_out);
}

// round 4
// speedup vs baseline: 2.4809x; 1.7595x over previous
#include <cuda_runtime.h>
#include <math_constants.h>

#define WML    64
#define BATCH  64
#define SENTS  40
#define DIM    512
#define NWORDS (SENTS * WML)   /* 2560 */

/* ------------------- scratch (static device memory; no allocs) -------- */
__device__ float g_qword[BATCH * DIM];
__device__ float g_qsent[BATCH * DIM];
__device__ float g_ssa[BATCH * SENTS];
__device__ float g_scores[BATCH * NWORDS];
__device__ float g_p[BATCH * NWORDS];
__device__ float g_partAcc[(size_t)BATCH * WML * DIM];   /* 8 MB */
__device__ float g_c[BATCH * DIM];

/* ------------------- K0: q_word / q_sent projections ------------------ */
__global__ void qproj_kernel(const float* __restrict__ src,
                             const float* __restrict__ Wword,
                             const float* __restrict__ Wsent) {
    const float* W   = blockIdx.y ? Wsent : Wword;
    float*       out = blockIdx.y ? g_qsent : g_qword;
    const int dt = blockIdx.x * 64;

    __shared__ float As[64][65];
    __shared__ float Bs[64][65];
    const int tid = threadIdx.x;
    const int tx = tid & 15, ty = tid >> 4;
    float acc[4][4] = {};

    for (int k0 = 0; k0 < DIM; k0 += 64) {
        for (int i = tid; i < 4096; i += 256) {
            int r = i >> 6, c = i & 63;
            As[r][c] = src[r * DIM + k0 + c];
            Bs[r][c] = W[(dt + r) * DIM + k0 + c];
        }
        __syncthreads();
        #pragma unroll 8
        for (int kk = 0; kk < 64; kk++) {
            float a[4], w[4];
            #pragma unroll
            for (int i = 0; i < 4; i++) a[i] = As[ty * 4 + i][kk];
            #pragma unroll
            for (int j = 0; j < 4; j++) w[j] = Bs[tx * 4 + j][kk];
            #pragma unroll
            for (int i = 0; i < 4; i++)
                #pragma unroll
                for (int j = 0; j < 4; j++) acc[i][j] += a[i] * w[j];
        }
        __syncthreads();
    }
    #pragma unroll
    for (int i = 0; i < 4; i++)
        #pragma unroll
        for (int j = 0; j < 4; j++)
            out[(ty * 4 + i) * DIM + dt + tx * 4 + j] = acc[i][j];
}

/* ------------------- K1: ssa[b][s] = (q_sent . sent_v) * static ------- */
__global__ void sentscore_kernel(const float* __restrict__ sent_bank,
                                 const float* __restrict__ static_attn) {
    const int b = blockIdx.x;
    const int tid = threadIdx.x;
    __shared__ float sq[DIM];
    for (int i = tid; i < DIM; i += 256) sq[i] = g_qsent[b * DIM + i];
    __syncthreads();

    const int wp = tid >> 5, ln = tid & 31;
    const float4* q4 = (const float4*)sq;
    for (int s = wp; s < SENTS; s += 8) {
        const float4* v4 = (const float4*)(sent_bank + ((size_t)s * BATCH + b) * DIM);
        float dot = 0.f;
        #pragma unroll
        for (int k = 0; k < 4; k++) {
            float4 q = q4[ln + 32 * k];
            float4 v = v4[ln + 32 * k];
            dot += q.x * v.x + q.y * v.y + q.z * v.z + q.w * v.w;
        }
        #pragma unroll
        for (int off = 16; off > 0; off >>= 1)
            dot += __shfl_xor_sync(0xffffffffu, dot, off);
        if (ln == 0) g_ssa[b * SENTS + s] = dot * static_attn[b * SENTS + s];
    }
}

/* ------------------- K2a: scores — pure stream, one warp per (w,b,s) -- */
/* grid (5, BATCH, WML) = 20480 CTAs, 256 thr. Masked words never load.  */
__global__ void __launch_bounds__(256)
score_kernel(const float* __restrict__ word_bank,
             const int*   __restrict__ word_lengths) {
    const int sc = blockIdx.x, b = blockIdx.y, w = blockIdx.z;
    const int tid = threadIdx.x, wp = tid >> 5, ln = tid & 31;
    const int s = sc * 8 + wp;

    __shared__ float sq[DIM];
    for (int i = tid; i < DIM; i += 256) sq[i] = g_qword[b * DIM + i];
    __syncthreads();

    float score = -CUDART_INF_F;
    if (w < word_lengths[b * SENTS + s]) {
        const float4* v4 = (const float4*)(word_bank
                           + (((size_t)w * BATCH + b) * SENTS + s) * (size_t)DIM);
        const float4* q4 = (const float4*)sq;
        float dot = 0.f;
        #pragma unroll
        for (int k = 0; k < 4; k++) {
            float4 v = __ldcs(v4 + ln + 32 * k);
            float4 q = q4[ln + 32 * k];
            dot += v.x * q.x + v.y * q.y + v.z * q.z + v.w * q.w;
        }
        #pragma unroll
        for (int off = 16; off > 0; off >>= 1)
            dot += __shfl_xor_sync(0xffffffffu, dot, off);
        score = dot * g_ssa[b * SENTS + s];
    }
    if (ln == 0)
        g_scores[(size_t)b * NWORDS + s * WML + w] = score;
}

/* ------------------- K2b: softmax per batch row ------------------------ */
/* grid BATCH, 512 thr; each thread handles 5 scores.                     */
__global__ void __launch_bounds__(512)
softmax_kernel(float* __restrict__ align_out, int has_align) {
    const int b = blockIdx.x, tid = threadIdx.x;
    const int wp = tid >> 5, ln = tid & 31;
    __shared__ float red[16];

    float v[5];
    #pragma unroll
    for (int k = 0; k < 5; k++)
        v[k] = g_scores[(size_t)b * NWORDS + tid + k * 512];

    /* block max */
    float mx = v[0];
    #pragma unroll
    for (int k = 1; k < 5; k++) mx = fmaxf(mx, v[k]);
    #pragma unroll
    for (int off = 16; off > 0; off >>= 1)
        mx = fmaxf(mx, __shfl_xor_sync(0xffffffffu, mx, off));
    if (ln == 0) red[wp] = mx;
    __syncthreads();
    if (wp == 0) {
        float m2 = (ln < 16) ? red[ln] : -CUDART_INF_F;
        #pragma unroll
        for (int off = 8; off > 0; off >>= 1)
            m2 = fmaxf(m2, __shfl_xor_sync(0xffffffffu, m2, off));
        if (ln == 0) red[0] = m2;
    }
    __syncthreads();
    const float M = red[0];
    __syncthreads();

    /* block sum */
    float p[5];
    float sum = 0.f;
    #pragma unroll
    for (int k = 0; k < 5; k++) {
        p[k] = __expf(v[k] - M);    /* -inf -> 0 */
        sum += p[k];
    }
    #pragma unroll
    for (int off = 16; off > 0; off >>= 1)
        sum += __shfl_xor_sync(0xffffffffu, sum, off);
    if (ln == 0) red[wp] = sum;
    __syncthreads();
    if (wp == 0) {
        float s2 = (ln < 16) ? red[ln] : 0.f;
        #pragma unroll
        for (int off = 8; off > 0; off >>= 1)
            s2 += __shfl_xor_sync(0xffffffffu, s2, off);
        if (ln == 0) red[0] = s2;
    }
    __syncthreads();
    const float invL = 1.f / red[0];

    #pragma unroll
    for (int k = 0; k < 5; k++) {
        const float pv = p[k] * invL + 1e-20f;
        g_p[(size_t)b * NWORDS + tid + k * 512] = pv;
        if (has_align)
            align_out[(size_t)b * NWORDS + tid + k * 512] = pv;
    }
}

/* ------------------- K2c: weighted sum — pure stream per (w,b) -------- */
/* grid (WML, BATCH), 128 thr; thread t owns float4 dim-slot t.          */
/* Compacts valid sentences, streams only those rows.                    */
__global__ void __launch_bounds__(128)
wsum_kernel(const float* __restrict__ word_bank) {
    const int w = blockIdx.x, b = blockIdx.y;
    const int tid = threadIdx.x;

    __shared__ float sp[SENTS];
    __shared__ int   slist[SENTS];
    __shared__ int   snum;

    if (tid < SENTS)
        sp[tid] = g_p[(size_t)b * NWORDS + tid * WML + w];
    __syncthreads();
    if (tid == 0) {
        int n = 0;
        for (int s = 0; s < SENTS; s++)
            if (sp[s] > 1.5e-20f) slist[n++] = s;
        snum = n;
    }
    __syncthreads();
    const int n = snum;

    const float4* base4 = (const float4*)(word_bank
                          + ((size_t)w * BATCH + b) * (size_t)(SENTS * DIM));
    float4 acc = {0.f, 0.f, 0.f, 0.f};
    int i = 0;
    for (; i + 4 <= n; i += 4) {
        const int s0 = slist[i],     s1 = slist[i + 1];
        const int s2 = slist[i + 2], s3 = slist[i + 3];
        const float p0 = sp[s0], p1 = sp[s1], p2 = sp[s2], p3 = sp[s3];
        float4 v0 = __ldcs(base4 + s0 * 128 + tid);
        float4 v1 = __ldcs(base4 + s1 * 128 + tid);
        float4 v2 = __ldcs(base4 + s2 * 128 + tid);
        float4 v3 = __ldcs(base4 + s3 * 128 + tid);
        acc.x += p0 * v0.x + p1 * v1.x + p2 * v2.x + p3 * v3.x;
        acc.y += p0 * v0.y + p1 * v1.y + p2 * v2.y + p3 * v3.y;
        acc.z += p0 * v0.z + p1 * v1.z + p2 * v2.z + p3 * v3.z;
        acc.w += p0 * v0.w + p1 * v1.w + p2 * v2.w + p3 * v3.w;
    }
    for (; i < n; i++) {
        const int s0 = slist[i];
        const float p0 = sp[s0];
        float4 v0 = __ldcs(base4 + s0 * 128 + tid);
        acc.x += p0 * v0.x; acc.y += p0 * v0.y;
        acc.z += p0 * v0.z; acc.w += p0 * v0.w;
    }
    float4* pa = (float4*)g_partAcc;
    pa[((size_t)b * WML + w) * 128 + tid] = acc;
}

/* ------------------- K2d: c[b][d] = sum_w partial ---------------------- */
__global__ void __launch_bounds__(512)
reducec_kernel() {
    const int b = blockIdx.x, d = threadIdx.x;
    float sum = 0.f;
    #pragma unroll 8
    for (int w = 0; w < WML; w++)
        sum += g_partAcc[((size_t)b * WML + w) * DIM + d];
    g_c[b * DIM + d] = sum;
}

/* ------------------- K3: attn_h = tanh([c, source] @ W_out^T) --------- */
__global__ void outproj_kernel(const float* __restrict__ src,
                               const float* __restrict__ Wout,
                               float* __restrict__ attn_out) {
    const int dt = blockIdx.x * 64;
    __shared__ float As[64][65];
    __shared__ float Bs[64][65];
    const int tid = threadIdx.x;
    const int tx = tid & 15, ty = tid >> 4;
    float acc[4][4] = {};

    for (int k0 = 0; k0 < 2 * DIM; k0 += 64) {
        for (int i = tid; i < 4096; i += 256) {
            int r = i >> 6, c = i & 63;
            int k = k0 + c;
            As[r][c] = (k < DIM) ? g_c[r * DIM + k] : src[r * DIM + (k - DIM)];
            Bs[r][c] = Wout[(dt + r) * (2 * DIM) + k];
        }
        __syncthreads();
        #pragma unroll 8
        for (int kk = 0; kk < 64; kk++) {
            float a[4], w[4];
            #pragma unroll
            for (int i = 0; i < 4; i++) a[i] = As[ty * 4 + i][kk];
            #pragma unroll
            for (int j = 0; j < 4; j++) w[j] = Bs[tx * 4 + j][kk];
            #pragma unroll
            for (int i = 0; i < 4; i++)
                #pragma unroll
                for (int j = 0; j < 4; j++) acc[i][j] += a[i] * w[j];
        }
        __syncthreads();
    }
    #pragma unroll
    for (int i = 0; i < 4; i++)
        #pragma unroll
        for (int j = 0; j < 4; j++)
            attn_out[(ty * 4 + i) * DIM + dt + tx * 4 + j] = tanhf(acc[i][j]);
}

/* ------------------- launch ------------------------------------------- */
extern "C" void kernel_launch(void* const* d_in, const int* in_sizes, int n_in,
                              void* d_out, int out_size) {
    const float* source       = (const float*)d_in[0];
    const float* word_bank    = (const float*)d_in[1];
    const int*   word_lengths = (const int*)  d_in[2];
    const float* sent_bank    = (const float*)d_in[3];
    /* d_in[4] = sent_lengths: unused by forward math */
    const float* static_attn  = (const float*)d_in[5];
    const float* W_word       = (const float*)d_in[6];
    const float* W_sent       = (const float*)d_in[7];
    const float* W_out        = (const float*)d_in[8];

    float* attn_out  = (float*)d_out;
    const int need   = BATCH * DIM + BATCH * NWORDS;
    const int has_align = (out_size >= need) ? 1 : 0;
    float* align_out = attn_out + BATCH * DIM;

    qproj_kernel<<<dim3(DIM / 64, 2), 256>>>(source, W_word, W_sent);
    sentscore_kernel<<<BATCH, 256>>>(sent_bank, static_attn);
    score_kernel<<<dim3(5, BATCH, WML), 256>>>(word_bank, word_lengths);
    softmax_kernel<<<BATCH, 512>>>(align_out, has_align);
    wsum_kernel<<<dim3(WML, BATCH), 128>>>(word_bank);
    reducec_kernel<<<BATCH, 512>>>();
    outproj_kernel<<<DIM / 64, 256>>>(source, W_out, attn_out);
}